// round 15
// baseline (speedup 1.0000x reference)
#include <cuda_runtime.h>
#include <cstdint>

#define BB 8
#define CC 256
#define HH 160
#define WW 160
#define HW (HH*WW)          // 25600

// edge kernel geometry: 32-col ALIGNED x 8-row tile; 8 warps split 256 channels
#define ETW 32
#define ETH 8
#define NXT 5               // 5*32 = 160, exact
#define NYT 20              // 20*8 = 160, exact
#define CPW 32              // channels per warp

// ---- scratch (no allocations allowed) ----
__device__ float g_c_sum[BB*CC];      // per-(b,c) sum of g
__device__ float g_w_gate[BB*CC];     // channel gate
__device__ float g_sum_x[BB*HW];      // per-pixel sum over channels of x
__device__ float g_sum_g[BB*HW];      // per-pixel sum over channels of g
__device__ float g_max_x[BB*HW];      // per-pixel max of x
__device__ float g_max_g[BB*HW];      // per-pixel max of g
__device__ float g_s_map[BB*HW];      // spatial gate
__device__ float g_ab[2];             // softplus(alpha), softplus(beta)

__device__ __forceinline__ float sqrt_approx(float v) {
    float r;
    asm("sqrt.approx.f32 %0, %1;" : "=f"(r) : "f"(v));
    return r;
}

// zero split across 3 launches so k_edge is the 4th launch (ncu capture slot)
__global__ void zkA() {                 // g_c_sum[0:1024]
    int i = blockIdx.x * 256 + threadIdx.x;
    if (i < 1024) g_c_sum[i] = 0.f;
}
__global__ void zkB() {                 // g_c_sum[1024:2048]
    int i = blockIdx.x * 256 + threadIdx.x;
    if (i < 1024) g_c_sum[1024 + i] = 0.f;
}
__global__ void zkC() {                 // g_ab (harmless; k_gates overwrites)
    if (threadIdx.x < 2 && blockIdx.x == 0) g_ab[threadIdx.x] = 0.f;
}

// horizontal Sobel stage for one row (R8 shfl version)
#define HROW(PTR, ROK, HD, HS, VOUT)                                   \
    {                                                                  \
        float v_ = (ROK) ? (PTR)[0] : 0.f;                             \
        float e_ = ((ROK) && eact) ? (PTR)[eoff] : 0.f;                \
        float xl_ = __shfl_up_sync(0xffffffffu, v_, 1);                \
        if (lane == 0)  xl_ = e_;                                      \
        float xr_ = __shfl_down_sync(0xffffffffu, v_, 1);              \
        if (lane == 31) xr_ = e_;                                      \
        HD = xl_ - xr_;                                                \
        HS = fmaf(2.f, v_, xl_) + xr_;                                 \
        VOUT = v_;                                                     \
    }

// ---------------------------------------------------------------------------
// Kernel 1 (4th launch): Sobel magnitude + all reductions — exact R8 version.
// Aligned 32-col tiles, lane == column, rolling 3-row window, shfl horizontal
// stage, butterfly channel reduce, two-phase cross-warp combine.
// grid (5, 20, 8), block 256.
// ---------------------------------------------------------------------------
__global__ __launch_bounds__(256) void k_edge(const float* __restrict__ x) {
    __shared__ float buf[8*520];            // [warp][stat(2)][260 pad]

    const int tid  = threadIdx.x;
    const int lane = tid & 31;
    const int wid  = tid >> 5;
    const int tx0  = blockIdx.x * ETW;
    const int ry0  = blockIdx.y * ETH;
    const int b    = blockIdx.z;

    const int col = tx0 + lane;             // always < WW
    const bool eact = ((lane == 0) && (col > 0)) ||
                      ((lane == 31) && (col + 1 < WW));
    const int  eoff = (lane == 0) ? -1 : 1;

    float sx[ETH], sg[ETH], mx[ETH], mg[ETH];
    #pragma unroll
    for (int k = 0; k < ETH; k++) {
        sx[k] = 0.f; sg[k] = 0.f; mx[k] = -3.4e38f; mg[k] = 0.f;
    }

    const bool rm1ok = (ry0 > 0);
    const bool rp8ok = (ry0 + ETH < HH);

    const float* xb = x + ((size_t)b * CC + (size_t)wid * CPW) * HW + col;

    for (int ch = 0; ch < CPW; ch++) {
        const float* xc = xb + (size_t)ch * HW;
        float cs = 0.f;

        float hdA, hsA, hdB, hsB, xprev, dmy;
        HROW(xc + (size_t)(ry0-1)*WW, rm1ok, hdA, hsA, dmy)
        HROW(xc + (size_t)ry0*WW,     true,  hdB, hsB, xprev)
        (void)dmy;

        #pragma unroll
        for (int k = 0; k < ETH; k++) {
            bool rok = (k < ETH-1) || rp8ok;      // row ry0+k+1
            float hdC, hsC, v;
            HROW(xc + (size_t)(ry0+k+1)*WW, rok, hdC, hsC, v)

            float gx = fmaf(2.f, hdB, hdA) + hdC;  // 4*true gx
            float gy = hsA - hsC;                  // 4*true gy
            float g  = 0.25f * sqrt_approx(fmaf(gy, gy, fmaf(gx, gx, 1.6e-11f)));

            sx[k] += xprev;  mx[k] = fmaxf(mx[k], xprev);
            sg[k] += g;      mg[k] = fmaxf(mg[k], g);
            cs += g;

            hdA = hdB; hdB = hdC; hsA = hsB; hsB = hsC; xprev = v;
        }

        // per-channel spatial sum (all lanes valid)
        #pragma unroll
        for (int off = 16; off; off >>= 1)
            cs += __shfl_xor_sync(0xffffffffu, cs, off);
        if (lane == 0)
            atomicAdd(&g_c_sum[b*CC + wid*CPW + ch], cs);
    }

    // two-phase cross-warp combine (sx,mx then sg,mg)
    const int pbase = b * HW + ry0 * WW + tx0;
    {
        float* mybuf = buf + wid * 520;
        #pragma unroll
        for (int k = 0; k < ETH; k++) {
            int px = k * 32 + lane;
            mybuf[px]       = sx[k];
            mybuf[260 + px] = mx[k];
        }
    }
    __syncthreads();
    {
        float rs = buf[tid], rm = buf[260 + tid];
        #pragma unroll
        for (int w = 1; w < 8; w++) {
            rs += buf[w*520 + tid];
            rm = fmaxf(rm, buf[w*520 + 260 + tid]);
        }
        int p = pbase + (tid >> 5) * WW + (tid & 31);
        g_sum_x[p] = rs;
        g_max_x[p] = rm;
    }
    __syncthreads();
    {
        float* mybuf = buf + wid * 520;
        #pragma unroll
        for (int k = 0; k < ETH; k++) {
            int px = k * 32 + lane;
            mybuf[px]       = sg[k];
            mybuf[260 + px] = mg[k];
        }
    }
    __syncthreads();
    {
        float rs = buf[tid], rm = buf[260 + tid];
        #pragma unroll
        for (int w = 1; w < 8; w++) {
            rs += buf[w*520 + tid];
            rm = fmaxf(rm, buf[w*520 + 260 + tid]);
        }
        int p = pbase + (tid >> 5) * WW + (tid & 31);
        g_sum_g[p] = rs;
        g_max_g[p] = rm;
    }
}

// ---------------------------------------------------------------------------
// Kernel 2: fused gates. Blocks 0..799: spatial 7x7 conv (16x16 tiles).
// Blocks 800..807: channel MLP for batch (blk-800). block = 256.
// ---------------------------------------------------------------------------
#define STILE 16
#define SHALO 22
#define SHE (SHALO*SHALO)    // 484
__global__ __launch_bounds__(256) void k_gates(const float* __restrict__ w1,
                                               const float* __restrict__ w2,
                                               const float* __restrict__ sw,
                                               const float* __restrict__ sb,
                                               const float* __restrict__ alpha,
                                               const float* __restrict__ beta) {
    __shared__ float sm[4*SHE + 200];
    const int tid = threadIdx.x;
    const int blk = blockIdx.x;

    if (blk < 800) {
        const int bx = blk % 10, by = (blk / 10) % 10, b = blk / 100;
        const int tx0 = bx * STILE, ty0 = by * STILE;
        float* t   = sm;
        float* wsm = sm + 4*SHE;
        if (tid < 196) wsm[tid] = sw[tid];

        const int pbase = b * HW;
        const float invC = 1.f / CC;
        for (int i = tid; i < 4*SHE; i += 256) {
            int ch  = i / SHE;
            int rem = i - ch * SHE;
            int r   = rem / SHALO, cc2 = rem - r * SHALO;
            int gy  = ty0 - 3 + r, gx = tx0 - 3 + cc2;
            float v = 0.f;
            if ((unsigned)gy < HH && (unsigned)gx < WW) {
                int p = pbase + gy * WW + gx;
                if      (ch == 0) v = g_sum_x[p] * invC;
                else if (ch == 1) v = g_max_x[p];
                else if (ch == 2) v = g_sum_g[p] * invC;
                else              v = g_max_g[p];
            }
            t[i] = v;
        }
        __syncthreads();

        const int pr = tid >> 4, pc = tid & 15;
        float acc = sb[0];
        #pragma unroll
        for (int ch = 0; ch < 4; ch++) {
            #pragma unroll
            for (int u = 0; u < 7; u++) {
                const float* rp = &t[ch*SHE + (pr + u)*SHALO + pc];
                const float* wr = &wsm[ch*49 + u*7];
                #pragma unroll
                for (int v = 0; v < 7; v++) acc = fmaf(rp[v], wr[v], acc);
            }
        }
        g_s_map[pbase + (ty0 + pr)*WW + tx0 + pc] = 1.f / (1.f + __expf(-acc));
    } else {
        const int b = blk - 800;
        float* cv = sm;
        float* h  = sm + CC;
        cv[tid] = g_c_sum[b*CC + tid] * (1.f / HW);
        __syncthreads();
        if (tid < 16) {
            float acc = 0.f;
            for (int c2 = 0; c2 < CC; c2++) acc = fmaf(cv[c2], w1[tid*CC + c2], acc);
            h[tid] = fmaxf(acc, 0.f);
        }
        __syncthreads();
        float acc = 0.f;
        #pragma unroll
        for (int j = 0; j < 16; j++) acc = fmaf(h[j], w2[tid*16 + j], acc);
        g_w_gate[b*CC + tid] = 1.f / (1.f + __expf(-acc));
        if (b == 0 && tid == 0) {
            float av = alpha[0], bv = beta[0];
            g_ab[0] = (av > 20.f) ? av : log1pf(expf(av));
            g_ab[1] = (bv > 20.f) ? bv : log1pf(expf(bv));
        }
    }
}

// ---------------------------------------------------------------------------
// Kernel 3: streaming apply. out = x * (1 + a*s) * (1 + b*w). float4,
// streaming cache hints (no reuse of x or out).
// ---------------------------------------------------------------------------
__global__ __launch_bounds__(256) void k_apply(const float* __restrict__ x,
                                               float* __restrict__ out) {
    const float a  = g_ab[0];
    const float bb = g_ab[1];
    const int hw4  = HW / 4;             // 6400
    int i4 = blockIdx.x * 256 + threadIdx.x;
    int cl = i4 / hw4;                   // b*CC + c   (0..2047)
    int b  = cl >> 8;
    int p4 = i4 - cl * hw4;
    float wg = fmaf(bb, g_w_gate[cl], 1.f);
    float4 s4 = ((const float4*)g_s_map)[b*hw4 + p4];
    float4 x4 = __ldcs((const float4*)x + i4);
    float4 o;
    o.x = x4.x * fmaf(a, s4.x, 1.f) * wg;
    o.y = x4.y * fmaf(a, s4.y, 1.f) * wg;
    o.z = x4.z * fmaf(a, s4.z, 1.f) * wg;
    o.w = x4.w * fmaf(a, s4.w, 1.f) * wg;
    __stcs((float4*)out + i4, o);
}

// ---------------------------------------------------------------------------
extern "C" void kernel_launch(void* const* d_in, const int* in_sizes, int n_in,
                              void* d_out, int out_size) {
    const float* x  = (const float*)d_in[0];
    const float* w1 = (const float*)d_in[1];
    const float* w2 = (const float*)d_in[2];
    const float* sw = (const float*)d_in[3];
    const float* sb = (const float*)d_in[4];
    const float* al = (const float*)d_in[5];
    const float* be = (const float*)d_in[6];
    float* out = (float*)d_out;

    // launches 1-3: split zero init (positions k_edge as the 4th launch,
    // which is the ncu capture slot)
    zkA<<<4, 256>>>();
    zkB<<<4, 256>>>();
    zkC<<<1, 32>>>();
    // launch 4: the kernel we need profiled
    dim3 g1(NXT, NYT, BB);
    k_edge<<<g1, 256>>>(x);
    // launches 5-6
    k_gates<<<808, 256>>>(w1, w2, sw, sb, al, be);
    int total4 = BB * CC * HW / 4;
    k_apply<<<(total4 + 255)/256, 256>>>(x, out);
}

// round 16
// speedup vs baseline: 1.1683x; 1.1683x over previous
#include <cuda_runtime.h>
#include <cstdint>

#define BB 8
#define CC 256
#define HH 160
#define WW 160
#define HW (HH*WW)          // 25600

// edge kernel geometry: 32-col ALIGNED x 8-row tile;
// NG=2 channel groups per (b,tile); 8 warps x 16 channels per block.
#define ETW 32
#define ETH 8
#define NXT 5               // 5*32 = 160, exact
#define NYT 20              // 20*8 = 160, exact
#define NG  2               // channel groups -> grid 1600 (90% wave fill)
#define CPW 16              // channels per warp

// ---- scratch (no allocations allowed) ----
__device__ float    g_c_sum[BB*CC];   // per-(b,c) sum of g
__device__ float    g_w_gate[BB*CC];  // channel gate
__device__ float    g_sum_x[BB*HW];   // per-pixel sum over channels of x
__device__ float    g_sum_g[BB*HW];   // per-pixel sum over channels of g
__device__ unsigned g_max_x[BB*HW];   // ordered-uint max of x
__device__ unsigned g_max_g[BB*HW];   // ordered-uint max of g
__device__ float    g_s_map[BB*HW];   // spatial gate
__device__ float    g_ab[2];          // softplus(alpha), softplus(beta)

__device__ __forceinline__ float sqrt_approx(float v) {
    float r;
    asm("sqrt.approx.f32 %0, %1;" : "=f"(r) : "f"(v));
    return r;
}
// monotone float<->uint order map (0u is below every mapped value)
__device__ __forceinline__ unsigned omap(float f) {
    unsigned u = __float_as_uint(f);
    return (u & 0x80000000u) ? ~u : (u | 0x80000000u);
}
__device__ __forceinline__ float ounmap(unsigned u) {
    return __uint_as_float((u & 0x80000000u) ? (u ^ 0x80000000u) : ~u);
}

// zero init split across 3 launches (keeps k_edge in the ncu capture slot,
// launch #4) — together they zero all accumulation buffers.
__global__ void zkA() {                 // g_sum_x, g_sum_g
    int i = blockIdx.x * 256 + threadIdx.x;
    if (i < BB*HW) { g_sum_x[i] = 0.f; g_sum_g[i] = 0.f; }
}
__global__ void zkB() {                 // g_max_x, g_max_g
    int i = blockIdx.x * 256 + threadIdx.x;
    if (i < BB*HW) { g_max_x[i] = 0u; g_max_g[i] = 0u; }
}
__global__ void zkC() {                 // g_c_sum
    int i = blockIdx.x * 256 + threadIdx.x;
    if (i < BB*CC) g_c_sum[i] = 0.f;
}

// horizontal Sobel stage for one row (shfl version, aligned main load)
#define HROW(PTR, ROK, HD, HS, VOUT)                                   \
    {                                                                  \
        float v_ = (ROK) ? (PTR)[0] : 0.f;                             \
        float e_ = ((ROK) && eact) ? (PTR)[eoff] : 0.f;                \
        float xl_ = __shfl_up_sync(0xffffffffu, v_, 1);                \
        if (lane == 0)  xl_ = e_;                                      \
        float xr_ = __shfl_down_sync(0xffffffffu, v_, 1);              \
        if (lane == 31) xr_ = e_;                                      \
        HD = xl_ - xr_;                                                \
        HS = fmaf(2.f, v_, xl_) + xr_;                                 \
        VOUT = v_;                                                     \
    }

// ---------------------------------------------------------------------------
// Kernel 1 (4th launch): Sobel magnitude + all reductions.
// R8 structure; channel work split 2 ways across blocks (NG=2) so the grid
// is 1600 blocks: at 4 blocks/SM (64 regs) capacity is 592 resident, and
// 1600 -> 2.7 waves at ~90% fill vs 800 -> 2 waves at 67%.
// Per-pixel stats combined across the two half-channel blocks via global
// atomicAdd / ordered-uint atomicMax. grid (5, 20, 16), block 256.
// ---------------------------------------------------------------------------
__global__ __launch_bounds__(256) void k_edge(const float* __restrict__ x) {
    __shared__ float buf[8*520];            // [warp][stat(2)][260 pad]

    const int tid  = threadIdx.x;
    const int lane = tid & 31;
    const int wid  = tid >> 5;
    const int tx0  = blockIdx.x * ETW;
    const int ry0  = blockIdx.y * ETH;
    const int bz   = blockIdx.z;
    const int b    = bz >> 1;               // NG = 2
    const int cbase = (bz & 1) * (CC/NG);   // 0 or 128

    const int col = tx0 + lane;             // always < WW
    const bool eact = ((lane == 0) && (col > 0)) ||
                      ((lane == 31) && (col + 1 < WW));
    const int  eoff = (lane == 0) ? -1 : 1;

    float sx[ETH], sg[ETH], mx[ETH], mg[ETH];
    #pragma unroll
    for (int k = 0; k < ETH; k++) {
        sx[k] = 0.f; sg[k] = 0.f; mx[k] = -3.4e38f; mg[k] = 0.f;
    }

    const bool rm1ok = (ry0 > 0);
    const bool rp8ok = (ry0 + ETH < HH);

    const float* xb = x + ((size_t)b * CC + cbase + (size_t)wid * CPW) * HW + col;

    for (int ch = 0; ch < CPW; ch++) {
        const float* xc = xb + (size_t)ch * HW;
        float cs = 0.f;

        float hdA, hsA, hdB, hsB, xprev, dmy;
        HROW(xc + (size_t)(ry0-1)*WW, rm1ok, hdA, hsA, dmy)
        HROW(xc + (size_t)ry0*WW,     true,  hdB, hsB, xprev)
        (void)dmy;

        #pragma unroll
        for (int k = 0; k < ETH; k++) {
            bool rok = (k < ETH-1) || rp8ok;      // row ry0+k+1
            float hdC, hsC, v;
            HROW(xc + (size_t)(ry0+k+1)*WW, rok, hdC, hsC, v)

            float gx = fmaf(2.f, hdB, hdA) + hdC;  // 4*true gx
            float gy = hsA - hsC;                  // 4*true gy
            float g  = 0.25f * sqrt_approx(fmaf(gy, gy, fmaf(gx, gx, 1.6e-11f)));

            sx[k] += xprev;  mx[k] = fmaxf(mx[k], xprev);
            sg[k] += g;      mg[k] = fmaxf(mg[k], g);
            cs += g;

            hdA = hdB; hdB = hdC; hsA = hsB; hsB = hsC; xprev = v;
        }

        // per-channel spatial sum
        #pragma unroll
        for (int off = 16; off; off >>= 1)
            cs += __shfl_xor_sync(0xffffffffu, cs, off);
        if (lane == 0)
            atomicAdd(&g_c_sum[b*CC + cbase + wid*CPW + ch], cs);
    }

    // two-phase cross-warp combine (sx,mx then sg,mg), then global atomics
    const int pbase = b * HW + ry0 * WW + tx0;
    const int pdst  = pbase + (tid >> 5) * WW + (tid & 31);
    {
        float* mybuf = buf + wid * 520;
        #pragma unroll
        for (int k = 0; k < ETH; k++) {
            int px = k * 32 + lane;
            mybuf[px]       = sx[k];
            mybuf[260 + px] = mx[k];
        }
    }
    __syncthreads();
    {
        float rs = buf[tid], rm = buf[260 + tid];
        #pragma unroll
        for (int w = 1; w < 8; w++) {
            rs += buf[w*520 + tid];
            rm = fmaxf(rm, buf[w*520 + 260 + tid]);
        }
        atomicAdd(&g_sum_x[pdst], rs);
        atomicMax(&g_max_x[pdst], omap(rm));
    }
    __syncthreads();
    {
        float* mybuf = buf + wid * 520;
        #pragma unroll
        for (int k = 0; k < ETH; k++) {
            int px = k * 32 + lane;
            mybuf[px]       = sg[k];
            mybuf[260 + px] = mg[k];
        }
    }
    __syncthreads();
    {
        float rs = buf[tid], rm = buf[260 + tid];
        #pragma unroll
        for (int w = 1; w < 8; w++) {
            rs += buf[w*520 + tid];
            rm = fmaxf(rm, buf[w*520 + 260 + tid]);
        }
        atomicAdd(&g_sum_g[pdst], rs);
        atomicMax(&g_max_g[pdst], omap(rm));
    }
}

// ---------------------------------------------------------------------------
// Kernel 2: fused gates. Blocks 0..799: spatial 7x7 conv (16x16 tiles).
// Blocks 800..807: channel MLP for batch (blk-800). block = 256.
// ---------------------------------------------------------------------------
#define STILE 16
#define SHALO 22
#define SHE (SHALO*SHALO)    // 484
__global__ __launch_bounds__(256) void k_gates(const float* __restrict__ w1,
                                               const float* __restrict__ w2,
                                               const float* __restrict__ sw,
                                               const float* __restrict__ sb,
                                               const float* __restrict__ alpha,
                                               const float* __restrict__ beta) {
    __shared__ float sm[4*SHE + 200];
    const int tid = threadIdx.x;
    const int blk = blockIdx.x;

    if (blk < 800) {
        const int bx = blk % 10, by = (blk / 10) % 10, b = blk / 100;
        const int tx0 = bx * STILE, ty0 = by * STILE;
        float* t   = sm;
        float* wsm = sm + 4*SHE;
        if (tid < 196) wsm[tid] = sw[tid];

        const int pbase = b * HW;
        const float invC = 1.f / CC;
        for (int i = tid; i < 4*SHE; i += 256) {
            int ch  = i / SHE;
            int rem = i - ch * SHE;
            int r   = rem / SHALO, cc2 = rem - r * SHALO;
            int gy  = ty0 - 3 + r, gx = tx0 - 3 + cc2;
            float v = 0.f;
            if ((unsigned)gy < HH && (unsigned)gx < WW) {
                int p = pbase + gy * WW + gx;
                if      (ch == 0) v = g_sum_x[p] * invC;
                else if (ch == 1) v = ounmap(g_max_x[p]);
                else if (ch == 2) v = g_sum_g[p] * invC;
                else              v = ounmap(g_max_g[p]);
            }
            t[i] = v;
        }
        __syncthreads();

        const int pr = tid >> 4, pc = tid & 15;
        float acc = sb[0];
        #pragma unroll
        for (int ch = 0; ch < 4; ch++) {
            #pragma unroll
            for (int u = 0; u < 7; u++) {
                const float* rp = &t[ch*SHE + (pr + u)*SHALO + pc];
                const float* wr = &wsm[ch*49 + u*7];
                #pragma unroll
                for (int v = 0; v < 7; v++) acc = fmaf(rp[v], wr[v], acc);
            }
        }
        g_s_map[pbase + (ty0 + pr)*WW + tx0 + pc] = 1.f / (1.f + __expf(-acc));
    } else {
        const int b = blk - 800;
        float* cv = sm;
        float* h  = sm + CC;
        cv[tid] = g_c_sum[b*CC + tid] * (1.f / HW);
        __syncthreads();
        if (tid < 16) {
            float acc = 0.f;
            for (int c2 = 0; c2 < CC; c2++) acc = fmaf(cv[c2], w1[tid*CC + c2], acc);
            h[tid] = fmaxf(acc, 0.f);
        }
        __syncthreads();
        float acc = 0.f;
        #pragma unroll
        for (int j = 0; j < 16; j++) acc = fmaf(h[j], w2[tid*16 + j], acc);
        g_w_gate[b*CC + tid] = 1.f / (1.f + __expf(-acc));
        if (b == 0 && tid == 0) {
            float av = alpha[0], bv = beta[0];
            g_ab[0] = (av > 20.f) ? av : log1pf(expf(av));
            g_ab[1] = (bv > 20.f) ? bv : log1pf(expf(bv));
        }
    }
}

// ---------------------------------------------------------------------------
// Kernel 3: streaming apply. out = x * (1 + a*s) * (1 + b*w). float4,
// streaming cache hints (no reuse of x or out).
// ---------------------------------------------------------------------------
__global__ __launch_bounds__(256) void k_apply(const float* __restrict__ x,
                                               float* __restrict__ out) {
    const float a  = g_ab[0];
    const float bb = g_ab[1];
    const int hw4  = HW / 4;             // 6400
    int i4 = blockIdx.x * 256 + threadIdx.x;
    int cl = i4 / hw4;                   // b*CC + c   (0..2047)
    int b  = cl >> 8;
    int p4 = i4 - cl * hw4;
    float wg = fmaf(bb, g_w_gate[cl], 1.f);
    float4 s4 = ((const float4*)g_s_map)[b*hw4 + p4];
    float4 x4 = __ldcs((const float4*)x + i4);
    float4 o;
    o.x = x4.x * fmaf(a, s4.x, 1.f) * wg;
    o.y = x4.y * fmaf(a, s4.y, 1.f) * wg;
    o.z = x4.z * fmaf(a, s4.z, 1.f) * wg;
    o.w = x4.w * fmaf(a, s4.w, 1.f) * wg;
    __stcs((float4*)out + i4, o);
}

// ---------------------------------------------------------------------------
extern "C" void kernel_launch(void* const* d_in, const int* in_sizes, int n_in,
                              void* d_out, int out_size) {
    const float* x  = (const float*)d_in[0];
    const float* w1 = (const float*)d_in[1];
    const float* w2 = (const float*)d_in[2];
    const float* sw = (const float*)d_in[3];
    const float* sb = (const float*)d_in[4];
    const float* al = (const float*)d_in[5];
    const float* be = (const float*)d_in[6];
    float* out = (float*)d_out;

    // launches 1-3: zero accumulators (and keep k_edge in ncu capture slot 4)
    zkA<<<(BB*HW + 255)/256, 256>>>();
    zkB<<<(BB*HW + 255)/256, 256>>>();
    zkC<<<(BB*CC + 255)/256, 256>>>();
    // launch 4: profiled kernel
    dim3 g1(NXT, NYT, BB*NG);
    k_edge<<<g1, 256>>>(x);
    // launches 5-6
    k_gates<<<808, 256>>>(w1, w2, sw, sb, al, be);
    int total4 = BB * CC * HW / 4;
    k_apply<<<(total4 + 255)/256, 256>>>(x, out);
}

// round 17
// speedup vs baseline: 1.5238x; 1.3042x over previous
#include <cuda_runtime.h>
#include <cstdint>

#define BB 8
#define CC 256
#define HH 160
#define WW 160
#define HW (HH*WW)          // 25600

// edge kernel geometry: 32-col ALIGNED x 4-row tile; NG=2 channel groups;
// 8 warps x 16 channels per block; batched register loads per channel.
#define ETW 32
#define ETH 4
#define NROW (ETH+2)        // 6 input rows per channel
#define NXT 5               // 5*32 = 160, exact
#define NYT 40              // 40*4 = 160, exact
#define NG  2               // grid z = BB*NG = 16 -> 3200 blocks
#define CPW 16              // channels per warp

// ---- scratch (no allocations allowed) ----
__device__ float    g_c_sum[BB*CC];   // per-(b,c) sum of g
__device__ float    g_w_gate[BB*CC];  // channel gate
__device__ float    g_sum_x[BB*HW];   // per-pixel sum over channels of x
__device__ float    g_sum_g[BB*HW];   // per-pixel sum over channels of g
__device__ unsigned g_max_x[BB*HW];   // ordered-uint max of x
__device__ unsigned g_max_g[BB*HW];   // ordered-uint max of g
__device__ float    g_s_map[BB*HW];   // spatial gate
__device__ float    g_ab[2];          // softplus(alpha), softplus(beta)

__device__ __forceinline__ float sqrt_approx(float v) {
    float r;
    asm("sqrt.approx.f32 %0, %1;" : "=f"(r) : "f"(v));
    return r;
}
// monotone float<->uint order map (0u is below every mapped value)
__device__ __forceinline__ unsigned omap(float f) {
    unsigned u = __float_as_uint(f);
    return (u & 0x80000000u) ? ~u : (u | 0x80000000u);
}
__device__ __forceinline__ float ounmap(unsigned u) {
    return __uint_as_float((u & 0x80000000u) ? (u ^ 0x80000000u) : ~u);
}

// zero init split across 3 launches (keeps k_edge in the ncu capture slot #4)
__global__ void zkA() {                 // g_sum_x, g_sum_g
    int i = blockIdx.x * 256 + threadIdx.x;
    if (i < BB*HW) { g_sum_x[i] = 0.f; g_sum_g[i] = 0.f; }
}
__global__ void zkB() {                 // g_max_x, g_max_g
    int i = blockIdx.x * 256 + threadIdx.x;
    if (i < BB*HW) { g_max_x[i] = 0u; g_max_g[i] = 0u; }
}
__global__ void zkC() {                 // g_c_sum
    int i = blockIdx.x * 256 + threadIdx.x;
    if (i < BB*CC) g_c_sum[i] = 0.f;
}

// horizontal Sobel stage from REGISTERS (loads already done)
#define HROWR(V, E, HD, HS)                                            \
    {                                                                  \
        float xl_ = __shfl_up_sync(0xffffffffu, (V), 1);               \
        if (lane == 0)  xl_ = (E);                                     \
        float xr_ = __shfl_down_sync(0xffffffffu, (V), 1);             \
        if (lane == 31) xr_ = (E);                                     \
        HD = xl_ - xr_;                                                \
        HS = fmaf(2.f, (V), xl_) + xr_;                                \
    }

// ---------------------------------------------------------------------------
// Kernel 1 (4th launch): Sobel magnitude + all reductions.
// Batched-load restructure: per channel, ALL 6 row loads + 6 edge loads are
// issued as independent LDGs into registers BEFORE any shuffle/compute, so
// memory latency is exposed once per channel, not once per row. ETH=4 keeps
// persistent stats at 16 regs (total ~50 -> 5 blocks/SM). NG=2 channel
// split; per-pixel stats combined via global atomics.
// grid (5, 40, 16) = 3200 blocks, block 256.
// ---------------------------------------------------------------------------
__global__ __launch_bounds__(256) void k_edge(const float* __restrict__ x) {
    __shared__ float buf[8*264];            // [warp][stat(2)][128 px pad 132]

    const int tid  = threadIdx.x;
    const int lane = tid & 31;
    const int wid  = tid >> 5;
    const int tx0  = blockIdx.x * ETW;
    const int ry0  = blockIdx.y * ETH;
    const int bz   = blockIdx.z;
    const int b    = bz >> 1;               // NG = 2
    const int cbase = (bz & 1) * (CC/NG);   // 0 or 128

    const int col = tx0 + lane;             // always < WW
    const bool eact = ((lane == 0) && (col > 0)) ||
                      ((lane == 31) && (col + 1 < WW));
    const int  eoff = (lane == 0) ? -1 : 1;

    float sx[ETH], sg[ETH], mx[ETH], mg[ETH];
    #pragma unroll
    for (int k = 0; k < ETH; k++) {
        sx[k] = 0.f; sg[k] = 0.f; mx[k] = -3.4e38f; mg[k] = 0.f;
    }

    // row validity flags for input rows ry0-1 .. ry0+4
    bool rowok[NROW];
    #pragma unroll
    for (int i = 0; i < NROW; i++) rowok[i] = true;
    rowok[0]      = (ry0 > 0);
    rowok[NROW-1] = (ry0 + ETH < HH);

    const float* xb = x + ((size_t)b * CC + cbase + (size_t)wid * CPW) * HW + col;

    for (int ch = 0; ch < CPW; ch++) {
        const float* xc = xb + (size_t)ch * HW + (size_t)(ry0 - 1) * WW;

        // ---- phase 1: batched independent loads (12 LDGs, MLP-friendly) ----
        float r[NROW], e[NROW];
        #pragma unroll
        for (int i = 0; i < NROW; i++) {
            r[i] = rowok[i] ? xc[i * WW] : 0.f;
            e[i] = (rowok[i] && eact) ? xc[i * WW + eoff] : 0.f;
        }

        // ---- phase 2: compute entirely from registers ----
        float cs = 0.f;
        float hdA, hsA, hdB, hsB;
        HROWR(r[0], e[0], hdA, hsA)
        HROWR(r[1], e[1], hdB, hsB)

        #pragma unroll
        for (int k = 0; k < ETH; k++) {
            float hdC, hsC;
            HROWR(r[k+2], e[k+2], hdC, hsC)

            float gx = fmaf(2.f, hdB, hdA) + hdC;  // 4*true gx
            float gy = hsA - hsC;                  // 4*true gy
            float g  = 0.25f * sqrt_approx(fmaf(gy, gy, fmaf(gx, gx, 1.6e-11f)));

            float xc_ = r[k+1];
            sx[k] += xc_;  mx[k] = fmaxf(mx[k], xc_);
            sg[k] += g;    mg[k] = fmaxf(mg[k], g);
            cs += g;

            hdA = hdB; hdB = hdC; hsA = hsB; hsB = hsC;
        }

        // per-channel spatial sum
        #pragma unroll
        for (int off = 16; off; off >>= 1)
            cs += __shfl_xor_sync(0xffffffffu, cs, off);
        if (lane == 0)
            atomicAdd(&g_c_sum[b*CC + cbase + wid*CPW + ch], cs);
    }

    // two-phase cross-warp combine (sx,mx then sg,mg), then global atomics
    const int pbase = b * HW + ry0 * WW + tx0;
    const int px    = tid & 127;            // 0..127 (4 rows x 32 cols)
    const int stat  = tid >> 7;             // 0 = sum, 1 = max
    const int pdst  = pbase + (px >> 5) * WW + (px & 31);
    {
        float* mybuf = buf + wid * 264;
        #pragma unroll
        for (int k = 0; k < ETH; k++) {
            int q = k * 32 + lane;
            mybuf[q]       = sx[k];
            mybuf[132 + q] = mx[k];
        }
    }
    __syncthreads();
    {
        float v = buf[stat*132 + px];
        if (stat == 0) {
            #pragma unroll
            for (int w = 1; w < 8; w++) v += buf[w*264 + px];
            atomicAdd(&g_sum_x[pdst], v);
        } else {
            #pragma unroll
            for (int w = 1; w < 8; w++) v = fmaxf(v, buf[w*264 + 132 + px]);
            atomicMax(&g_max_x[pdst], omap(v));
        }
    }
    __syncthreads();
    {
        float* mybuf = buf + wid * 264;
        #pragma unroll
        for (int k = 0; k < ETH; k++) {
            int q = k * 32 + lane;
            mybuf[q]       = sg[k];
            mybuf[132 + q] = mg[k];
        }
    }
    __syncthreads();
    {
        float v = buf[stat*132 + px];
        if (stat == 0) {
            #pragma unroll
            for (int w = 1; w < 8; w++) v += buf[w*264 + px];
            atomicAdd(&g_sum_g[pdst], v);
        } else {
            #pragma unroll
            for (int w = 1; w < 8; w++) v = fmaxf(v, buf[w*264 + 132 + px]);
            atomicMax(&g_max_g[pdst], omap(v));
        }
    }
}

// ---------------------------------------------------------------------------
// Kernel 2: fused gates. Blocks 0..799: spatial 7x7 conv (16x16 tiles).
// Blocks 800..807: channel MLP for batch (blk-800). block = 256.
// ---------------------------------------------------------------------------
#define STILE 16
#define SHALO 22
#define SHE (SHALO*SHALO)    // 484
__global__ __launch_bounds__(256) void k_gates(const float* __restrict__ w1,
                                               const float* __restrict__ w2,
                                               const float* __restrict__ sw,
                                               const float* __restrict__ sb,
                                               const float* __restrict__ alpha,
                                               const float* __restrict__ beta) {
    __shared__ float sm[4*SHE + 200];
    const int tid = threadIdx.x;
    const int blk = blockIdx.x;

    if (blk < 800) {
        const int bx = blk % 10, by = (blk / 10) % 10, b = blk / 100;
        const int tx0 = bx * STILE, ty0 = by * STILE;
        float* t   = sm;
        float* wsm = sm + 4*SHE;
        if (tid < 196) wsm[tid] = sw[tid];

        const int pbase = b * HW;
        const float invC = 1.f / CC;
        for (int i = tid; i < 4*SHE; i += 256) {
            int ch  = i / SHE;
            int rem = i - ch * SHE;
            int r   = rem / SHALO, cc2 = rem - r * SHALO;
            int gy  = ty0 - 3 + r, gx = tx0 - 3 + cc2;
            float v = 0.f;
            if ((unsigned)gy < HH && (unsigned)gx < WW) {
                int p = pbase + gy * WW + gx;
                if      (ch == 0) v = g_sum_x[p] * invC;
                else if (ch == 1) v = ounmap(g_max_x[p]);
                else if (ch == 2) v = g_sum_g[p] * invC;
                else              v = ounmap(g_max_g[p]);
            }
            t[i] = v;
        }
        __syncthreads();

        const int pr = tid >> 4, pc = tid & 15;
        float acc = sb[0];
        #pragma unroll
        for (int ch = 0; ch < 4; ch++) {
            #pragma unroll
            for (int u = 0; u < 7; u++) {
                const float* rp = &t[ch*SHE + (pr + u)*SHALO + pc];
                const float* wr = &wsm[ch*49 + u*7];
                #pragma unroll
                for (int v = 0; v < 7; v++) acc = fmaf(rp[v], wr[v], acc);
            }
        }
        g_s_map[pbase + (ty0 + pr)*WW + tx0 + pc] = 1.f / (1.f + __expf(-acc));
    } else {
        const int b = blk - 800;
        float* cv = sm;
        float* h  = sm + CC;
        cv[tid] = g_c_sum[b*CC + tid] * (1.f / HW);
        __syncthreads();
        if (tid < 16) {
            float acc = 0.f;
            for (int c2 = 0; c2 < CC; c2++) acc = fmaf(cv[c2], w1[tid*CC + c2], acc);
            h[tid] = fmaxf(acc, 0.f);
        }
        __syncthreads();
        float acc = 0.f;
        #pragma unroll
        for (int j = 0; j < 16; j++) acc = fmaf(h[j], w2[tid*16 + j], acc);
        g_w_gate[b*CC + tid] = 1.f / (1.f + __expf(-acc));
        if (b == 0 && tid == 0) {
            float av = alpha[0], bv = beta[0];
            g_ab[0] = (av > 20.f) ? av : log1pf(expf(av));
            g_ab[1] = (bv > 20.f) ? bv : log1pf(expf(bv));
        }
    }
}

// ---------------------------------------------------------------------------
// Kernel 3: streaming apply. out = x * (1 + a*s) * (1 + b*w). float4,
// streaming cache hints (no reuse of x or out).
// ---------------------------------------------------------------------------
__global__ __launch_bounds__(256) void k_apply(const float* __restrict__ x,
                                               float* __restrict__ out) {
    const float a  = g_ab[0];
    const float bb = g_ab[1];
    const int hw4  = HW / 4;             // 6400
    int i4 = blockIdx.x * 256 + threadIdx.x;
    int cl = i4 / hw4;                   // b*CC + c   (0..2047)
    int b  = cl >> 8;
    int p4 = i4 - cl * hw4;
    float wg = fmaf(bb, g_w_gate[cl], 1.f);
    float4 s4 = ((const float4*)g_s_map)[b*hw4 + p4];
    float4 x4 = __ldcs((const float4*)x + i4);
    float4 o;
    o.x = x4.x * fmaf(a, s4.x, 1.f) * wg;
    o.y = x4.y * fmaf(a, s4.y, 1.f) * wg;
    o.z = x4.z * fmaf(a, s4.z, 1.f) * wg;
    o.w = x4.w * fmaf(a, s4.w, 1.f) * wg;
    __stcs((float4*)out + i4, o);
}

// ---------------------------------------------------------------------------
extern "C" void kernel_launch(void* const* d_in, const int* in_sizes, int n_in,
                              void* d_out, int out_size) {
    const float* x  = (const float*)d_in[0];
    const float* w1 = (const float*)d_in[1];
    const float* w2 = (const float*)d_in[2];
    const float* sw = (const float*)d_in[3];
    const float* sb = (const float*)d_in[4];
    const float* al = (const float*)d_in[5];
    const float* be = (const float*)d_in[6];
    float* out = (float*)d_out;

    // launches 1-3: zero accumulators (k_edge stays in ncu capture slot 4)
    zkA<<<(BB*HW + 255)/256, 256>>>();
    zkB<<<(BB*HW + 255)/256, 256>>>();
    zkC<<<(BB*CC + 255)/256, 256>>>();
    // launch 4: profiled kernel
    dim3 g1(NXT, NYT, BB*NG);
    k_edge<<<g1, 256>>>(x);
    // launches 5-6
    k_gates<<<808, 256>>>(w1, w2, sw, sb, al, be);
    int total4 = BB * CC * HW / 4;
    k_apply<<<(total4 + 255)/256, 256>>>(x, out);
}